// round 3
// baseline (speedup 1.0000x reference)
#include <cuda_runtime.h>

#define N_NODES  200000
#define N_EDGES  3200000
#define N_PAIRS  4096
#define FEAT     32
#define CONCAT   128
#define SCAN_BLK 1024
#define NB_SCAN  196   // ceil(200000/1024)
#define LAYER_BLOCKS 296
#define LAYER_WARPS  (LAYER_BLOCKS * 8)

// ---- scratch (device globals; no allocation allowed) ----
__device__ int   g_count[N_NODES];
__device__ int   g_offsets[N_NODES];
__device__ int   g_pos[N_EDGES];
__device__ int   g_adj[N_EDGES];
__device__ float g_invdeg[N_NODES];
// decoupled-lookback state
__device__ int g_tile_state[NB_SCAN];   // 0=empty 1=agg 2=prefix
__device__ int g_tile_agg[NB_SCAN];
__device__ int g_tile_incl[NB_SCAN];

// ---------------- init (replaces memset; keeps launch count tight) ----------------
__global__ void init_kernel() {
    int i = blockIdx.x * blockDim.x + threadIdx.x;
    if (i < N_NODES) g_count[i] = 0;
    if (i < NB_SCAN) g_tile_state[i] = 0;
}

// ---------------- CSR build ----------------
__global__ void hist_kernel(const int* __restrict__ dst) {
    int e = blockIdx.x * blockDim.x + threadIdx.x;
    if (e < N_EDGES) g_pos[e] = atomicAdd(&g_count[dst[e]], 1);
}

// single-pass exclusive scan over g_count (decoupled lookback) + invdeg
__global__ void scan_kernel() {
    __shared__ int s[SCAN_BLK];
    __shared__ int s_prefix;
    int b = blockIdx.x;
    int tid = threadIdx.x;
    int i = b * SCAN_BLK + tid;
    int v = (i < N_NODES) ? g_count[i] : 0;
    s[tid] = v;
    __syncthreads();
    for (int d = 1; d < SCAN_BLK; d <<= 1) {
        int t = (tid >= d) ? s[tid - d] : 0;
        __syncthreads();
        if (tid >= d) s[tid] += t;
        __syncthreads();
    }
    if (tid == 0) {
        int total = s[SCAN_BLK - 1];
        g_tile_agg[b] = total;
        __threadfence();
        if (b > 0) atomicExch(&g_tile_state[b], 1);
        // lookback
        int running = 0;
        if (b > 0) {
            int j = b - 1;
            while (true) {
                int st;
                do { st = atomicAdd(&g_tile_state[j], 0); } while (st == 0);
                if (st == 2) { running += g_tile_incl[j]; break; }
                running += g_tile_agg[j];
                if (j == 0) break;
                j--;
            }
        }
        s_prefix = running;
        g_tile_incl[b] = running + total;
        __threadfence();
        atomicExch(&g_tile_state[b], 2);
    }
    __syncthreads();
    if (i < N_NODES) {
        g_offsets[i] = s_prefix + s[tid] - v;  // exclusive
        g_invdeg[i]  = 1.0f / fmaxf((float)v, 1.0f);
    }
}

__global__ void fill_kernel(const int* __restrict__ src, const int* __restrict__ dst) {
    int e = blockIdx.x * blockDim.x + threadIdx.x;
    if (e < N_EDGES) g_adj[g_offsets[dst[e]] + g_pos[e]] = src[e];
}

// ---------------- fused SAGE layer (persistent, register-resident weights) ----------------
// Grid-strided warps, ~85 nodes/warp. Each thread owns output column `lane` of
// [Ws;Wn] in 64 registers (amortized over all nodes). Gather: lane=(g,c),
// g=lane>>3 one of 4 simultaneous neighbors, c=lane&7 float4 chunk -> each warp
// LDG.128 pulls 4 full rows. Epilogue: stage h||mean (64 floats) in per-warp
// smem, matvec = 16 LDS.128 broadcasts + 64 FFMA. No shuffles in epilogue.
__global__ __launch_bounds__(256, 2) void layer_kernel(
        const float* __restrict__ hin, int stride,
        float* __restrict__ hout,              // concat + l*32, row stride 128
        const float* __restrict__ Ws,
        const float* __restrict__ Wn,
        const float* __restrict__ b) {
    __shared__ float sHM[8][64];
    const unsigned FULL = 0xffffffffu;
    int tid  = threadIdx.x;
    int lane = tid & 31;
    int w    = tid >> 5;
    int g = lane >> 3;
    int c = lane & 7;

    float wreg[64];
#pragma unroll
    for (int k = 0; k < 32; k++) wreg[k]      = __ldg(&Ws[k * 32 + lane]);
#pragma unroll
    for (int k = 0; k < 32; k++) wreg[32 + k] = __ldg(&Wn[k * 32 + lane]);
    float breg = __ldg(&b[lane]);

    for (int node = blockIdx.x * 8 + w; node < N_NODES; node += LAYER_WARPS) {
        int beg = g_offsets[node];
        int cnt = g_count[node];
        int end = beg + cnt;

        float4 acc0 = make_float4(0.f, 0.f, 0.f, 0.f);
        float4 acc1 = make_float4(0.f, 0.f, 0.f, 0.f);

        for (int base = beg; base < end; base += 32) {
            int a = (base + lane < end) ? g_adj[base + lane] : 0;
            int nrem = end - base;      // uniform across warp
#pragma unroll
            for (int j = 0; j < 8; j++) {
                if (j * 4 >= nrem) break;
                int nidx = j * 4 + g;
                int s = __shfl_sync(FULL, a, nidx);
                if (nidx < nrem) {
                    float4 v = __ldg((const float4*)(hin + (size_t)s * stride) + c);
                    if (j & 1) {
                        acc1.x += v.x; acc1.y += v.y; acc1.z += v.z; acc1.w += v.w;
                    } else {
                        acc0.x += v.x; acc0.y += v.y; acc0.z += v.z; acc0.w += v.w;
                    }
                }
            }
        }
        acc0.x += acc1.x; acc0.y += acc1.y; acc0.z += acc1.z; acc0.w += acc1.w;
        // reduce across the 4 neighbor groups (lanes differing in bits 3,4)
#pragma unroll
        for (int off = 8; off <= 16; off <<= 1) {
            acc0.x += __shfl_xor_sync(FULL, acc0.x, off);
            acc0.y += __shfl_xor_sync(FULL, acc0.y, off);
            acc0.z += __shfl_xor_sync(FULL, acc0.z, off);
            acc0.w += __shfl_xor_sync(FULL, acc0.w, off);
        }
        float inv = g_invdeg[node];
        float hv  = __ldg(&hin[(size_t)node * stride + lane]);

        __syncwarp();   // prior-iteration LDS reads done before overwrite
        sHM[w][lane] = hv;
        if (lane < 8) {   // g==0 lanes hold mean feats 4c..4c+3 (replicated per group)
            ((float4*)&sHM[w][32])[lane] =
                make_float4(acc0.x * inv, acc0.y * inv, acc0.z * inv, acc0.w * inv);
        }
        __syncwarp();

        float o = breg;
#pragma unroll
        for (int k = 0; k < 16; k++) {
            float4 hm = ((const float4*)sHM[w])[k];
            o += hm.x * wreg[4 * k + 0] + hm.y * wreg[4 * k + 1]
               + hm.z * wreg[4 * k + 2] + hm.w * wreg[4 * k + 3];
        }
        hout[(size_t)node * CONCAT + lane] = tanhf(o);
    }
}

// ---------------- pair MLP ----------------
__global__ void mlp_kernel(const float* __restrict__ concat,
                           const int* __restrict__ user_idx,
                           const int* __restrict__ item_idx,
                           const float* __restrict__ W1,
                           const float* __restrict__ bl1,
                           const float* __restrict__ W2,
                           const float* __restrict__ bl2,
                           float* __restrict__ score) {
    const int PB = 32;
    __shared__ float sP[PB][256];
    __shared__ float sOut[PB];
    int tid = threadIdx.x;       // 0..127
    int p0  = blockIdx.x * PB;

    for (int idx = tid; idx < PB * 256; idx += 128) {
        int p = idx >> 8, k = idx & 255;
        int pair = p0 + p;
        int node = (k < 128) ? user_idx[pair] : item_idx[pair];
        sP[p][k] = concat[(size_t)node * 128 + (k & 127)];
    }
    if (tid < PB) sOut[tid] = 0.0f;
    __syncthreads();

    float acc[PB];
#pragma unroll
    for (int p = 0; p < PB; p++) acc[p] = 0.0f;

    for (int k = 0; k < 256; k++) {
        float wv = W1[k * 128 + tid];
#pragma unroll
        for (int p = 0; p < PB; p++) acc[p] += sP[p][k] * wv;
    }

    float bj = bl1[tid];
    float w2 = W2[tid];
#pragma unroll
    for (int p = 0; p < PB; p++) {
        float h = fmaxf(acc[p] + bj, 0.0f);
        atomicAdd(&sOut[p], h * w2);
    }
    __syncthreads();

    if (tid < PB) {
        float v = sOut[tid] + bl2[0];
        score[p0 + tid] = 1.0f / (1.0f + expf(-v));
    }
}

// ---------------- launch ----------------
extern "C" void kernel_launch(void* const* d_in, const int* in_sizes, int n_in,
                              void* d_out, int out_size) {
    const float* x        = (const float*)d_in[0];
    const int*   src      = (const int*)d_in[1];
    const int*   dst      = (const int*)d_in[2];
    const int*   user_idx = (const int*)d_in[3];
    const int*   item_idx = (const int*)d_in[4];
    const float* Ws[4]; const float* Wn[4]; const float* B[4];
    for (int l = 0; l < 4; l++) {
        Ws[l] = (const float*)d_in[5 + 3 * l];
        Wn[l] = (const float*)d_in[6 + 3 * l];
        B[l]  = (const float*)d_in[7 + 3 * l];
    }
    const float* W1  = (const float*)d_in[17];
    const float* bl1 = (const float*)d_in[18];
    const float* W2  = (const float*)d_in[19];
    const float* bl2 = (const float*)d_in[20];

    float* out    = (float*)d_out;
    float* score  = out;             // [N_PAIRS]
    float* concat = out + N_PAIRS;   // [N_NODES, 128]

    init_kernel<<<(N_NODES + 255) / 256, 256>>>();
    hist_kernel<<<(N_EDGES + 255) / 256, 256>>>(dst);
    scan_kernel<<<NB_SCAN, SCAN_BLK>>>();
    fill_kernel<<<(N_EDGES + 255) / 256, 256>>>(src, dst);

    layer_kernel<<<LAYER_BLOCKS, 256>>>(x,            32,  concat + 0,  Ws[0], Wn[0], B[0]);
    layer_kernel<<<LAYER_BLOCKS, 256>>>(concat + 0,   128, concat + 32, Ws[1], Wn[1], B[1]);
    layer_kernel<<<LAYER_BLOCKS, 256>>>(concat + 32,  128, concat + 64, Ws[2], Wn[2], B[2]);
    layer_kernel<<<LAYER_BLOCKS, 256>>>(concat + 64,  128, concat + 96, Ws[3], Wn[3], B[3]);

    mlp_kernel<<<N_PAIRS / 32, 128>>>(concat, user_idx, item_idx, W1, bl1, W2, bl2, score);
}

// round 4
// speedup vs baseline: 1.1090x; 1.1090x over previous
#include <cuda_runtime.h>

#define N_NODES  200000
#define N_EDGES  3200000
#define N_PAIRS  4096
#define FEAT     32
#define CONCAT   128
#define SCAN_BLK 1024
#define NB_SCAN  196   // ceil(200000/1024)
#define LAYER_BLOCKS 296
#define LAYER_WARPS  (LAYER_BLOCKS * 8)

// ---- scratch (device globals; zero-initialized at module load) ----
__device__ int   g_count[N_NODES];
__device__ int   g_offsets[N_NODES];
__device__ int   g_pos[N_EDGES];
__device__ int   g_adj[N_EDGES];
__device__ float g_invdeg[N_NODES];
// decoupled-lookback state
__device__ int g_tile_state[NB_SCAN];   // 0=empty 1=agg 2=prefix
__device__ int g_tile_agg[NB_SCAN];
__device__ int g_tile_incl[NB_SCAN];

// ---------------- CSR build ----------------
// g_count / g_tile_state are zero at entry: zero-init on first call,
// re-zeroed by cleanup_kernel at the end of every launch sequence.
__global__ void hist_kernel(const int* __restrict__ dst) {
    int e = blockIdx.x * blockDim.x + threadIdx.x;
    if (e < N_EDGES) g_pos[e] = atomicAdd(&g_count[dst[e]], 1);
}

// single-pass exclusive scan over g_count (decoupled lookback) + invdeg
__global__ void scan_kernel() {
    __shared__ int s[SCAN_BLK];
    __shared__ int s_prefix;
    int b = blockIdx.x;
    int tid = threadIdx.x;
    int i = b * SCAN_BLK + tid;
    int v = (i < N_NODES) ? g_count[i] : 0;
    s[tid] = v;
    __syncthreads();
    for (int d = 1; d < SCAN_BLK; d <<= 1) {
        int t = (tid >= d) ? s[tid - d] : 0;
        __syncthreads();
        if (tid >= d) s[tid] += t;
        __syncthreads();
    }
    if (tid == 0) {
        int total = s[SCAN_BLK - 1];
        g_tile_agg[b] = total;
        __threadfence();
        if (b > 0) atomicExch(&g_tile_state[b], 1);
        int running = 0;
        if (b > 0) {
            int j = b - 1;
            while (true) {
                int st;
                do { st = atomicAdd(&g_tile_state[j], 0); } while (st == 0);
                if (st == 2) { running += g_tile_incl[j]; break; }
                running += g_tile_agg[j];
                if (j == 0) break;
                j--;
            }
        }
        s_prefix = running;
        g_tile_incl[b] = running + total;
        __threadfence();
        atomicExch(&g_tile_state[b], 2);
    }
    __syncthreads();
    if (i < N_NODES) {
        g_offsets[i] = s_prefix + s[tid] - v;  // exclusive
        g_invdeg[i]  = 1.0f / fmaxf((float)v, 1.0f);
    }
}

__global__ void fill_kernel(const int* __restrict__ src, const int* __restrict__ dst) {
    int e = blockIdx.x * blockDim.x + threadIdx.x;
    if (e < N_EDGES) g_adj[g_offsets[dst[e]] + g_pos[e]] = src[e];
}

// ---------------- fused SAGE layer ----------------
// Persistent grid-strided warps (~85 nodes/warp). Each thread owns output
// column `lane` of [Ws;Wn] in 64 registers (amortized over all its nodes).
// Gather (R2-style, fully predicated — no break): lane=(g,c), g=lane>>3 picks
// one of 4 simultaneous neighbors, c=lane&7 picks the float4 chunk; each warp
// LDG.128 pulls 4 full 128B rows, 8 loads batched per 32-neighbor step.
// Epilogue: stage h||mean (64 floats) in per-warp smem, matvec = 16 LDS.128
// broadcasts + 64 FFMA. MIO ops per node ~18 (vs ~150 in R2).
__global__ __launch_bounds__(256, 2) void layer_kernel(
        const float* __restrict__ hin, int stride,
        float* __restrict__ hout,              // concat + l*32, row stride 128
        const float* __restrict__ Ws,
        const float* __restrict__ Wn,
        const float* __restrict__ b) {
    __shared__ float sHM[8][64];
    const unsigned FULL = 0xffffffffu;
    int tid  = threadIdx.x;
    int lane = tid & 31;
    int w    = tid >> 5;
    int g = lane >> 3;
    int c = lane & 7;

    float wreg[64];
#pragma unroll
    for (int k = 0; k < 32; k++) wreg[k]      = __ldg(&Ws[k * 32 + lane]);
#pragma unroll
    for (int k = 0; k < 32; k++) wreg[32 + k] = __ldg(&Wn[k * 32 + lane]);
    float breg = __ldg(&b[lane]);

    for (int node = blockIdx.x * 8 + w; node < N_NODES; node += LAYER_WARPS) {
        int beg = g_offsets[node];
        int end = beg + g_count[node];

        float4 acc0 = make_float4(0.f, 0.f, 0.f, 0.f);
        float4 acc1 = make_float4(0.f, 0.f, 0.f, 0.f);

        for (int base = beg; base < end; base += 32) {
            int a = (base + lane < end) ? g_adj[base + lane] : 0;
#pragma unroll
            for (int j = 0; j < 8; j++) {
                int nidx = j * 4 + g;
                int s = __shfl_sync(FULL, a, nidx);
                if (base + nidx < end) {
                    float4 v = __ldg((const float4*)(hin + (size_t)s * stride) + c);
                    if (j & 1) {
                        acc1.x += v.x; acc1.y += v.y; acc1.z += v.z; acc1.w += v.w;
                    } else {
                        acc0.x += v.x; acc0.y += v.y; acc0.z += v.z; acc0.w += v.w;
                    }
                }
            }
        }
        acc0.x += acc1.x; acc0.y += acc1.y; acc0.z += acc1.z; acc0.w += acc1.w;
        // reduce across the 4 neighbor groups (lanes differing in bits 3,4)
#pragma unroll
        for (int off = 8; off <= 16; off <<= 1) {
            acc0.x += __shfl_xor_sync(FULL, acc0.x, off);
            acc0.y += __shfl_xor_sync(FULL, acc0.y, off);
            acc0.z += __shfl_xor_sync(FULL, acc0.z, off);
            acc0.w += __shfl_xor_sync(FULL, acc0.w, off);
        }
        float inv = g_invdeg[node];
        float hv  = __ldg(&hin[(size_t)node * stride + lane]);

        __syncwarp();   // prior-iteration LDS reads done before overwrite
        sHM[w][lane] = hv;
        if (lane < 8) {   // g==0 lanes hold mean feats 4c..4c+3 (replicated per group)
            ((float4*)&sHM[w][32])[lane] =
                make_float4(acc0.x * inv, acc0.y * inv, acc0.z * inv, acc0.w * inv);
        }
        __syncwarp();

        float o = breg;
#pragma unroll
        for (int k = 0; k < 16; k++) {
            float4 hm = ((const float4*)sHM[w])[k];
            o += hm.x * wreg[4 * k + 0] + hm.y * wreg[4 * k + 1]
               + hm.z * wreg[4 * k + 2] + hm.w * wreg[4 * k + 3];
        }
        hout[(size_t)node * CONCAT + lane] = tanhf(o);
    }
}

// ---------------- pair MLP ----------------
__global__ void mlp_kernel(const float* __restrict__ concat,
                           const int* __restrict__ user_idx,
                           const int* __restrict__ item_idx,
                           const float* __restrict__ W1,
                           const float* __restrict__ bl1,
                           const float* __restrict__ W2,
                           const float* __restrict__ bl2,
                           float* __restrict__ score) {
    const int PB = 32;
    __shared__ float sP[PB][256];
    __shared__ float sOut[PB];
    int tid = threadIdx.x;       // 0..127
    int p0  = blockIdx.x * PB;

    for (int idx = tid; idx < PB * 256; idx += 128) {
        int p = idx >> 8, k = idx & 255;
        int pair = p0 + p;
        int node = (k < 128) ? user_idx[pair] : item_idx[pair];
        sP[p][k] = concat[(size_t)node * 128 + (k & 127)];
    }
    if (tid < PB) sOut[tid] = 0.0f;
    __syncthreads();

    float acc[PB];
#pragma unroll
    for (int p = 0; p < PB; p++) acc[p] = 0.0f;

    for (int k = 0; k < 256; k++) {
        float wv = W1[k * 128 + tid];
#pragma unroll
        for (int p = 0; p < PB; p++) acc[p] += sP[p][k] * wv;
    }

    float bj = bl1[tid];
    float w2 = W2[tid];
#pragma unroll
    for (int p = 0; p < PB; p++) {
        float h = fmaxf(acc[p] + bj, 0.0f);
        atomicAdd(&sOut[p], h * w2);
    }
    __syncthreads();

    if (tid < PB) {
        float v = sOut[tid] + bl2[0];
        score[p0 + tid] = 1.0f / (1.0f + expf(-v));
    }
}

// ---------------- cleanup: restore zero-state for the next replay ----------------
__global__ void cleanup_kernel() {
    int i = blockIdx.x * blockDim.x + threadIdx.x;
    if (i < N_NODES) g_count[i] = 0;
    if (i < NB_SCAN) g_tile_state[i] = 0;
}

// ---------------- launch ----------------
extern "C" void kernel_launch(void* const* d_in, const int* in_sizes, int n_in,
                              void* d_out, int out_size) {
    const float* x        = (const float*)d_in[0];
    const int*   src      = (const int*)d_in[1];
    const int*   dst      = (const int*)d_in[2];
    const int*   user_idx = (const int*)d_in[3];
    const int*   item_idx = (const int*)d_in[4];
    const float* Ws[4]; const float* Wn[4]; const float* B[4];
    for (int l = 0; l < 4; l++) {
        Ws[l] = (const float*)d_in[5 + 3 * l];
        Wn[l] = (const float*)d_in[6 + 3 * l];
        B[l]  = (const float*)d_in[7 + 3 * l];
    }
    const float* W1  = (const float*)d_in[17];
    const float* bl1 = (const float*)d_in[18];
    const float* W2  = (const float*)d_in[19];
    const float* bl2 = (const float*)d_in[20];

    float* out    = (float*)d_out;
    float* score  = out;             // [N_PAIRS]
    float* concat = out + N_PAIRS;   // [N_NODES, 128]

    hist_kernel<<<(N_EDGES + 255) / 256, 256>>>(dst);
    scan_kernel<<<NB_SCAN, SCAN_BLK>>>();
    fill_kernel<<<(N_EDGES + 255) / 256, 256>>>(src, dst);

    layer_kernel<<<LAYER_BLOCKS, 256>>>(x,            32,  concat + 0,  Ws[0], Wn[0], B[0]);
    layer_kernel<<<LAYER_BLOCKS, 256>>>(concat + 0,   128, concat + 32, Ws[1], Wn[1], B[1]);
    layer_kernel<<<LAYER_BLOCKS, 256>>>(concat + 32,  128, concat + 64, Ws[2], Wn[2], B[2]);
    layer_kernel<<<LAYER_BLOCKS, 256>>>(concat + 64,  128, concat + 96, Ws[3], Wn[3], B[3]);

    mlp_kernel<<<N_PAIRS / 32, 128>>>(concat, user_idx, item_idx, W1, bl1, W2, bl2, score);

    cleanup_kernel<<<(N_NODES + 255) / 256, 256>>>();
}